// round 3
// baseline (speedup 1.0000x reference)
#include <cuda_runtime.h>
#include <cuda_bf16.h>
#include <cstdint>

// Problem constants (match reference)
#define U_DIM 20000
#define I_DIM 10000
#define K_DIM 64
#define B_DIM 4096

// Output region offsets (floats), in reference return order:
// (S_hat*mask)[U,I], (P*mask)[U,K], (bu*mask)[U,1], (Q*mask)[I,K], (bi*mask)[I]
#define OFF_SHAT   0LL
#define N_SHAT     (200000000LL)                 // U*I
#define OFF_UF     (OFF_SHAT + N_SHAT)           // 200,000,000
#define N_UF       (1280000LL)                   // U*K
#define OFF_UB     (OFF_UF + N_UF)               // 201,280,000
#define N_UB       (20000LL)
#define OFF_IF     (OFF_UB + N_UB)               // 201,300,000
#define N_IF       (640000LL)                    // I*K
#define OFF_IB     (OFF_IF + N_IF)               // 201,940,000
#define N_IB       (10000LL)
#define N_TOTAL    (OFF_IB + N_IB)               // 201,950,000

// Compute blocks inside the fused kernel (run in wave 1, hide under zeroing)
#define CB         32
#define CB_THREADS 256
#define CB_WARPS   (CB * (CB_THREADS / 32))      // 256 warps

// ---------------------------------------------------------------------------
// Scratch staging (statically-declared device memory — no allocation).
// Fully rewritten each call -> deterministic under graph replay.
// ---------------------------------------------------------------------------
__device__ float g_urow[B_DIM * K_DIM];   // staged P rows   (1 MB)
__device__ float g_irow[B_DIM * K_DIM];   // staged Q rows   (1 MB)
__device__ float g_sval[B_DIM];           // dot + bu + bi   (16 KB)
__device__ float g_ub[B_DIM];             // bu[u] per entry
__device__ float g_ib[B_DIM];             // bi[i] per entry

// ---------------------------------------------------------------------------
// Kernel 1 (fused): blocks [0, CB) gather + compute into scratch (latency-
// heavy part, hidden under the zeroing); blocks [CB, ...) zero the output
// with float4 stores. Disjoint memory -> no intra-kernel ordering needed.
// ---------------------------------------------------------------------------
__global__ void mmf_fused_zero_compute(const float* __restrict__ P,   // [U,K]
                                       const float* __restrict__ Q,   // [I,K]
                                       const float* __restrict__ bu,  // [U]
                                       const float* __restrict__ bi,  // [I]
                                       const int* __restrict__ uidx,  // [B] i32
                                       const int* __restrict__ iidx,  // [B] i32
                                       float4* __restrict__ out4,
                                       long long n4) {
    if (blockIdx.x < CB) {
        // ---- compute/staging path (256 warps, 16 entries each) ----
        int wid  = (blockIdx.x * CB_THREADS + threadIdx.x) >> 5;
        int lane = threadIdx.x & 31;
        for (int e = wid; e < B_DIM; e += CB_WARPS) {
            long long u = (long long)uidx[e];
            long long i = (long long)iidx[e];

            const float* pu = P + u * K_DIM;
            const float* qi = Q + i * K_DIM;

            float a0 = pu[lane];
            float a1 = pu[lane + 32];
            float b0 = qi[lane];
            float b1 = qi[lane + 32];

            float s = fmaf(a0, b0, a1 * b1);
            #pragma unroll
            for (int off = 16; off; off >>= 1)
                s += __shfl_xor_sync(0xffffffffu, s, off);

            // stage rows contiguously
            g_urow[e * K_DIM + lane]      = a0;
            g_urow[e * K_DIM + lane + 32] = a1;
            g_irow[e * K_DIM + lane]      = b0;
            g_irow[e * K_DIM + lane + 32] = b1;

            if (lane == 0) {
                float bias_u = bu[u];
                float bias_i = bi[i];
                g_sval[e] = s + bias_u + bias_i;
                g_ub[e]   = bias_u;
                g_ib[e]   = bias_i;
            }
        }
    } else {
        // ---- zeroing path (store-bandwidth bound, the roofline) ----
        long long idx = (long long)(blockIdx.x - CB) * blockDim.x + threadIdx.x;
        if (idx < n4) {
            out4[idx] = make_float4(0.f, 0.f, 0.f, 0.f);
        }
    }
}

__global__ void mmf_zero_tail_kernel(float* __restrict__ out,
                                     long long start, long long n) {
    long long idx = start + (long long)blockIdx.x * blockDim.x + threadIdx.x;
    if (idx < n) out[idx] = 0.f;
}

// ---------------------------------------------------------------------------
// Kernel 2 (tail stub): store-only scatter from contiguous scratch. One warp
// per batch entry. No random-gather latency chains; stores are fire-and-
// forget into L2. Duplicate u/i/(u,i) write identical values (benign).
// ---------------------------------------------------------------------------
__global__ void mmf_scatter_stores(const int* __restrict__ uidx,
                                   const int* __restrict__ iidx,
                                   float* __restrict__ out) {
    int gtid = blockIdx.x * blockDim.x + threadIdx.x;
    int e    = gtid >> 5;
    int lane = gtid & 31;
    if (e >= B_DIM) return;

    long long u = (long long)uidx[e];
    long long i = (long long)iidx[e];

    float a0 = g_urow[e * K_DIM + lane];
    float a1 = g_urow[e * K_DIM + lane + 32];
    float b0 = g_irow[e * K_DIM + lane];
    float b1 = g_irow[e * K_DIM + lane + 32];

    float* out_uf = out + OFF_UF;
    float* out_ub = out + OFF_UB;
    float* out_if = out + OFF_IF;
    float* out_ib = out + OFF_IB;

    out_uf[u * K_DIM + lane]      = a0;
    out_uf[u * K_DIM + lane + 32] = a1;
    out_if[i * K_DIM + lane]      = b0;
    out_if[i * K_DIM + lane + 32] = b1;

    if (lane == 0) {
        out[u * (long long)I_DIM + i] = g_sval[e];
        out_ub[u] = g_ub[e];
        out_ib[i] = g_ib[e];
    }
}

// ---------------------------------------------------------------------------
// Launch.
// inputs (metadata order): user_factor_weight [U,K] f32, item_factor_weight
// [I,K] f32, user_bias [U,1] f32, item_bias [I] f32,
// users_idx [B] int32, items_idx [B] int32
// ---------------------------------------------------------------------------
extern "C" void kernel_launch(void* const* d_in, const int* in_sizes, int n_in,
                              void* d_out, int out_size) {
    const float* P    = (const float*)d_in[0];
    const float* Q    = (const float*)d_in[1];
    const float* bu   = (const float*)d_in[2];
    const float* bi   = (const float*)d_in[3];
    const int*   uidx = (const int*)d_in[4];
    const int*   iidx = (const int*)d_in[5];
    float* out = (float*)d_out;

    const long long n_total = (long long)out_size;   // expected 201,950,000
    const long long n4 = n_total / 4;

    // 1) fused: zero output (808 MB stores) + stage sparse values in scratch
    const int zthreads = CB_THREADS;
    const long long zblocks = CB + (n4 + zthreads - 1) / zthreads;
    mmf_fused_zero_compute<<<(unsigned)zblocks, zthreads>>>(
        P, Q, bu, bi, uidx, iidx, (float4*)out, n4);

    const long long tail_start = n4 * 4;
    if (tail_start < n_total) {
        mmf_zero_tail_kernel<<<1, 32>>>(out, tail_start, n_total);
    }

    // 2) store-only scatter from contiguous scratch (tail stub)
    const int sthreads = 256;                     // 8 warps/block
    const int sblocks  = (B_DIM * 32) / sthreads; // 512
    mmf_scatter_stores<<<sblocks, sthreads>>>(uidx, iidx, out);
}